// round 1
// baseline (speedup 1.0000x reference)
#include <cuda_runtime.h>
#include <math.h>

// Problem constants
#define B_   32
#define C_   128
#define N_   1024
#define S_   32

// Scratch (no cudaMalloc allowed)
__device__ float g_pos[32 * 1024];            // [32 ch][1024 n]
__device__ float g_q[32 * 128 * 1024];        // q = relu(Wq x0 + b), [B][128][N]

// ---------------------------------------------------------------------------
// Positional embedding, faithful to the numpy .view reinterpret:
// t is [32,16] row-major; xe channel j at row y = t_flat[j*32+y];
// ye channel j at col x = t_flat[j*32+x]. Channels: 0..15 xe, 16..31 ye.
// ---------------------------------------------------------------------------
__global__ void pos_kernel() {
    int idx = blockIdx.x * blockDim.x + threadIdx.x;
    if (idx >= 32 * 1024) return;
    int c = idx >> 10, n = idx & 1023;
    int y = n >> 5, x = n & 31;
    int i = (c < 16) ? (c * 32 + y) : ((c - 16) * 32 + x);
    int p = i >> 4, j = i & 15;
    float r = 0.0f;
    if (p != 0) {
        double denom = pow(10000.0, (double)(2 * (j >> 1)) / 16.0);
        double val = (double)p / denom;
        r = (j & 1) ? (float)cos(val) : (float)sin(val);
    }
    g_pos[idx] = r;
}

// ---------------------------------------------------------------------------
// Routed input read: virtual concat [x(128) | pos(32) | extra(128)]
// ---------------------------------------------------------------------------
__device__ __forceinline__ float load_in(const float* __restrict__ x,
                                         const float* __restrict__ extra,
                                         int b, int c, int n) {
    if (c < 128) return x[((size_t)(b * 128 + c)) * 1024 + n];
    if (c < 160) return g_pos[(c - 128) * 1024 + n];
    return extra[((size_t)(b * 128 + (c - 160))) * 1024 + n];
}

// ---------------------------------------------------------------------------
// q = relu(Wq @ [x|pos] + bq)    Wq: [128,160]
// grid (16, 2, 32), block 256; 64x64 tile, each thread 4x4
// ---------------------------------------------------------------------------
__global__ __launch_bounds__(256) void q_kernel(
    const float* __restrict__ x, const float* __restrict__ Wq,
    const float* __restrict__ bq)
{
    __shared__ float As[16][64];
    __shared__ float Bs[16][64];
    const int Cin = 160;
    int b = blockIdx.z, r0 = blockIdx.y * 64, n0 = blockIdx.x * 64;
    int t = threadIdx.x, ty = t >> 4, tx = t & 15;
    float acc[4][4] = {};

    for (int k0 = 0; k0 < Cin; k0 += 16) {
        #pragma unroll
        for (int e = 0; e < 4; e++) {
            int idx = t + 256 * e;
            int arow = idx >> 4, acol = idx & 15;
            As[acol][arow] = Wq[(size_t)(r0 + arow) * Cin + k0 + acol];
            int brow = idx >> 6, bcol = idx & 63;
            Bs[brow][bcol] = load_in(x, nullptr, b, k0 + brow, n0 + bcol);
        }
        __syncthreads();
        #pragma unroll
        for (int kk = 0; kk < 16; kk++) {
            float a[4], bb[4];
            #pragma unroll
            for (int i = 0; i < 4; i++) a[i] = As[kk][ty * 4 + i];
            #pragma unroll
            for (int j = 0; j < 4; j++) bb[j] = Bs[kk][tx * 4 + j];
            #pragma unroll
            for (int i = 0; i < 4; i++)
                #pragma unroll
                for (int j = 0; j < 4; j++)
                    acc[i][j] += a[i] * bb[j];
        }
        __syncthreads();
    }
    #pragma unroll
    for (int i = 0; i < 4; i++) {
        int r = r0 + ty * 4 + i;
        float bv = bq[r];
        #pragma unroll
        for (int j = 0; j < 4; j++) {
            int n = n0 + tx * 4 + j;
            g_q[((size_t)(b * 128 + r)) * 1024 + n] = fmaxf(acc[i][j] + bv, 0.0f);
        }
    }
}

// ---------------------------------------------------------------------------
// Gated highway update: out = sigmoid(Wf@x0e+bf) * extra + relu(Wc@x0e+bc)
// x0e = [x|pos|extra] (Cin=288). Shares the B-tile load between both GEMMs.
// ---------------------------------------------------------------------------
__global__ __launch_bounds__(256) void gated_kernel(
    const float* __restrict__ x, const float* __restrict__ extra,
    const float* __restrict__ Wf, const float* __restrict__ bf,
    const float* __restrict__ Wc, const float* __restrict__ bc,
    float* __restrict__ out)
{
    __shared__ float AsF[16][64];
    __shared__ float AsC[16][64];
    __shared__ float Bs[16][64];
    const int Cin = 288;
    int b = blockIdx.z, r0 = blockIdx.y * 64, n0 = blockIdx.x * 64;
    int t = threadIdx.x, ty = t >> 4, tx = t & 15;
    float accF[4][4] = {};
    float accC[4][4] = {};

    for (int k0 = 0; k0 < Cin; k0 += 16) {
        #pragma unroll
        for (int e = 0; e < 4; e++) {
            int idx = t + 256 * e;
            int arow = idx >> 4, acol = idx & 15;
            AsF[acol][arow] = Wf[(size_t)(r0 + arow) * Cin + k0 + acol];
            AsC[acol][arow] = Wc[(size_t)(r0 + arow) * Cin + k0 + acol];
            int brow = idx >> 6, bcol = idx & 63;
            Bs[brow][bcol] = load_in(x, extra, b, k0 + brow, n0 + bcol);
        }
        __syncthreads();
        #pragma unroll
        for (int kk = 0; kk < 16; kk++) {
            float af[4], ac[4], bb[4];
            #pragma unroll
            for (int i = 0; i < 4; i++) { af[i] = AsF[kk][ty * 4 + i]; ac[i] = AsC[kk][ty * 4 + i]; }
            #pragma unroll
            for (int j = 0; j < 4; j++) bb[j] = Bs[kk][tx * 4 + j];
            #pragma unroll
            for (int i = 0; i < 4; i++)
                #pragma unroll
                for (int j = 0; j < 4; j++) {
                    accF[i][j] += af[i] * bb[j];
                    accC[i][j] += ac[i] * bb[j];
                }
        }
        __syncthreads();
    }
    #pragma unroll
    for (int i = 0; i < 4; i++) {
        int r = r0 + ty * 4 + i;
        float bfv = bf[r], bcv = bc[r];
        #pragma unroll
        for (int j = 0; j < 4; j++) {
            int n = n0 + tx * 4 + j;
            float f = 1.0f / (1.0f + expf(-(accF[i][j] + bfv)));
            float cc = fmaxf(accC[i][j] + bcv, 0.0f);
            size_t off = ((size_t)(b * 128 + r)) * 1024 + n;
            out[off] = f * extra[off] + cc;
        }
    }
}

// ---------------------------------------------------------------------------
// Causal attention (flash style): per block one batch + 64 query rows.
// S = (q^T k)/sqrt(128) with causal mask (see_self); softmax online;
// out[v][n] = sum_m P[n][m] v[v][m]. Matches reference exactly since
// expf(-1e4 - max) == 0 in fp32.
// smem: Qs 32K + Ks 32K + Vs 32K + Ps(64x65) 16.25K + 3*256B = 113 KB
// ---------------------------------------------------------------------------
#define ATTN_SMEM_FLOATS (3 * 128 * 64 + 64 * 65 + 3 * 64)
#define ATTN_SMEM_BYTES  (ATTN_SMEM_FLOATS * 4)

__global__ __launch_bounds__(256) void attn_kernel(
    const float* __restrict__ k, const float* __restrict__ v,
    float* __restrict__ out)
{
    extern __shared__ float sm[];
    float* Qs = sm;                    // [128][64]
    float* Ks = Qs + 128 * 64;         // [128][64]
    float* Vs = Ks + 128 * 64;         // [128][64]
    float* Ps = Vs + 128 * 64;         // [64][65]
    float* rMax = Ps + 64 * 65;
    float* rSum = rMax + 64;
    float* rAlpha = rSum + 64;

    const int b = blockIdx.y;
    const int bx = blockIdx.x;
    const int n0 = bx * 64;
    const int t = threadIdx.x;
    const int ty = t >> 4, tx = t & 15;     // S-phase mapping (4n x 4m)
    const int tn = t & 15, tv = t >> 4;     // O-phase mapping (4n x 8v)
    const float scale = 0.08838834764831845f;  // 1/sqrt(128)

    // Load Q tile (from g_q)
    #pragma unroll
    for (int e = 0; e < 32; e++) {
        int idx = t + 256 * e;
        int c = idx >> 6, nn = idx & 63;
        Qs[c * 64 + nn] = g_q[((size_t)(b * 128 + c)) * 1024 + n0 + nn];
    }
    if (t < 64) { rMax[t] = -1e30f; rSum[t] = 0.0f; }
    __syncthreads();

    float O[4][8];
    #pragma unroll
    for (int i = 0; i < 4; i++)
        #pragma unroll
        for (int j = 0; j < 8; j++) O[i][j] = 0.0f;

    for (int mt = 0; mt <= bx; mt++) {
        const int m0 = mt * 64;
        // Load K, V tiles
        #pragma unroll
        for (int e = 0; e < 32; e++) {
            int idx = t + 256 * e;
            int c = idx >> 6, mm = idx & 63;
            Ks[c * 64 + mm] = k[((size_t)(b * 128 + c)) * 1024 + m0 + mm];
            Vs[c * 64 + mm] = v[((size_t)(b * 128 + c)) * 1024 + m0 + mm];
        }
        __syncthreads();

        // S = Q^T K  (contraction over 128 channels)
        float Sacc[4][4] = {};
        #pragma unroll 4
        for (int c = 0; c < 128; c++) {
            float qv[4], kv[4];
            #pragma unroll
            for (int i = 0; i < 4; i++) qv[i] = Qs[c * 64 + ty * 4 + i];
            #pragma unroll
            for (int j = 0; j < 4; j++) kv[j] = Ks[c * 64 + tx * 4 + j];
            #pragma unroll
            for (int i = 0; i < 4; i++)
                #pragma unroll
                for (int j = 0; j < 4; j++)
                    Sacc[i][j] += qv[i] * kv[j];
        }
        const bool diag = (mt == bx);
        #pragma unroll
        for (int i = 0; i < 4; i++)
            #pragma unroll
            for (int j = 0; j < 4; j++) {
                float sv = Sacc[i][j] * scale;
                if (diag && (tx * 4 + j) > (ty * 4 + i)) sv = -1e30f;
                Ps[(ty * 4 + i) * 65 + tx * 4 + j] = sv;
            }
        __syncthreads();

        // Online softmax update (64 rows, one thread per row)
        if (t < 64) {
            float rm = rMax[t];
            float tm = -1e30f;
            #pragma unroll 8
            for (int m = 0; m < 64; m++) tm = fmaxf(tm, Ps[t * 65 + m]);
            float nm = fmaxf(rm, tm);
            float alpha = expf(rm - nm);
            float psum = 0.0f;
            #pragma unroll 8
            for (int m = 0; m < 64; m++) {
                float p = expf(Ps[t * 65 + m] - nm);
                Ps[t * 65 + m] = p;
                psum += p;
            }
            rSum[t] = rSum[t] * alpha + psum;
            rMax[t] = nm;
            rAlpha[t] = alpha;
        }
        __syncthreads();

        // O = O*alpha + P @ V^T
        float a[4];
        #pragma unroll
        for (int i = 0; i < 4; i++) a[i] = rAlpha[tn * 4 + i];
        #pragma unroll
        for (int i = 0; i < 4; i++)
            #pragma unroll
            for (int j = 0; j < 8; j++) O[i][j] *= a[i];
        #pragma unroll 4
        for (int m = 0; m < 64; m++) {
            float pv[4], vv[8];
            #pragma unroll
            for (int i = 0; i < 4; i++) pv[i] = Ps[(tn * 4 + i) * 65 + m];
            #pragma unroll
            for (int j = 0; j < 8; j++) vv[j] = Vs[(tv * 8 + j) * 64 + m];
            #pragma unroll
            for (int i = 0; i < 4; i++)
                #pragma unroll
                for (int j = 0; j < 8; j++)
                    O[i][j] += pv[i] * vv[j];
        }
        __syncthreads();
    }

    // Normalize and store: out[b][v][n]
    #pragma unroll
    for (int i = 0; i < 4; i++) {
        float inv = 1.0f / rSum[tn * 4 + i];
        int n = n0 + tn * 4 + i;
        #pragma unroll
        for (int j = 0; j < 8; j++) {
            int vc = tv * 8 + j;
            out[((size_t)(b * 128 + vc)) * 1024 + n] = O[i][j] * inv;
        }
    }
}

// ---------------------------------------------------------------------------
// Launch
// Inputs: 0:x 1:k 2:v 3:W_q 4:b_q 5:W_fk 6:b_fk 7:W_ck 8:b_ck
//         9:W_fv 10:b_fv 11:W_cv 12:b_cv 13:W_fc(dead) 14:b_fc(dead)
// Output: [out2 | k_new | v_new], each 32*128*1024 floats
// ---------------------------------------------------------------------------
extern "C" void kernel_launch(void* const* d_in, const int* in_sizes, int n_in,
                              void* d_out, int out_size)
{
    const float* x   = (const float*)d_in[0];
    const float* k   = (const float*)d_in[1];
    const float* v   = (const float*)d_in[2];
    const float* Wq  = (const float*)d_in[3];
    const float* bq  = (const float*)d_in[4];
    const float* Wfk = (const float*)d_in[5];
    const float* bfk = (const float*)d_in[6];
    const float* Wck = (const float*)d_in[7];
    const float* bck = (const float*)d_in[8];
    const float* Wfv = (const float*)d_in[9];
    const float* bfv = (const float*)d_in[10];
    const float* Wcv = (const float*)d_in[11];
    const float* bcv = (const float*)d_in[12];

    float* out2 = (float*)d_out;
    float* kn   = out2 + (size_t)32 * 128 * 1024;
    float* vn   = kn   + (size_t)32 * 128 * 1024;

    pos_kernel<<<32, 1024>>>();
    q_kernel<<<dim3(16, 2, 32), 256>>>(x, Wq, bq);
    gated_kernel<<<dim3(16, 2, 32), 256>>>(x, k, Wfk, bfk, Wck, bck, kn);
    gated_kernel<<<dim3(16, 2, 32), 256>>>(x, v, Wfv, bfv, Wcv, bcv, vn);

    cudaFuncSetAttribute(attn_kernel,
                         cudaFuncAttributeMaxDynamicSharedMemorySize,
                         ATTN_SMEM_BYTES);
    attn_kernel<<<dim3(16, 32), 256, ATTN_SMEM_BYTES>>>(k, v, out2);
}

// round 2
// speedup vs baseline: 1.2434x; 1.2434x over previous
#include <cuda_runtime.h>
#include <math.h>
#include <stdint.h>

// ---------------------------------------------------------------------------
// Scratch (no cudaMalloc allowed)
// ---------------------------------------------------------------------------
__device__ float g_pos[32 * 1024];            // [32 ch][1024 n]
__device__ float g_q[32 * 128 * 1024];        // q = tf32(relu(Wq x0 + b)), [B][128][N]

// ---------------------------------------------------------------------------
// tf32 helpers (mma.sync m16n8k8, fp32 accumulate)
// ---------------------------------------------------------------------------
__device__ __forceinline__ uint32_t f2tf(float x) {
    uint32_t u;
    asm("cvt.rna.tf32.f32 %0, %1;" : "=r"(u) : "f"(x));
    return u;
}
__device__ __forceinline__ void mma_tf32(
    float& d0, float& d1, float& d2, float& d3,
    uint32_t a0, uint32_t a1, uint32_t a2, uint32_t a3,
    uint32_t b0, uint32_t b1)
{
    asm volatile(
        "mma.sync.aligned.m16n8k8.row.col.f32.tf32.tf32.f32 "
        "{%0,%1,%2,%3}, {%4,%5,%6,%7}, {%8,%9}, {%0,%1,%2,%3};"
        : "+f"(d0), "+f"(d1), "+f"(d2), "+f"(d3)
        : "r"(a0), "r"(a1), "r"(a2), "r"(a3), "r"(b0), "r"(b1));
}

// ---------------------------------------------------------------------------
// Positional embedding, faithful to the numpy .view reinterpret
// ---------------------------------------------------------------------------
__global__ void pos_kernel() {
    int idx = blockIdx.x * blockDim.x + threadIdx.x;
    if (idx >= 32 * 1024) return;
    int c = idx >> 10, n = idx & 1023;
    int y = n >> 5, x = n & 31;
    int i = (c < 16) ? (c * 32 + y) : ((c - 16) * 32 + x);
    int p = i >> 4, j = i & 15;
    float r = 0.0f;
    if (p != 0) {
        double denom = pow(10000.0, (double)(2 * (j >> 1)) / 16.0);
        double val = (double)p / denom;
        r = (j & 1) ? (float)cos(val) : (float)sin(val);
    }
    g_pos[idx] = r;
}

// Routed input read: virtual concat [x(128) | pos(32) | extra(128)]
__device__ __forceinline__ float load_in(const float* __restrict__ x,
                                         const float* __restrict__ extra,
                                         int b, int c, int n) {
    if (c < 128) return x[((size_t)(b * 128 + c)) * 1024 + n];
    if (c < 160) return g_pos[(c - 128) * 1024 + n];
    return extra[((size_t)(b * 128 + (c - 160))) * 1024 + n];
}

// ---------------------------------------------------------------------------
// Gated highway update on tensor cores.
// out = sigmoid(Wf@X + bf) * extra + relu(Wc@X + bc), X = [x|pos|extra] (288)
// Block: 64 out-rows x 128 spatial, 8 warps (2M x 4N), warp tile 32x32.
// ---------------------------------------------------------------------------
#define GSA 36    // A smem stride (32 k + 4), 36 % 32 == 4
#define GSB 136   // B smem stride (128 n + 8), 136 % 32 == 8

__global__ __launch_bounds__(256) void gated_kernel(
    const float* __restrict__ x, const float* __restrict__ extra,
    const float* __restrict__ Wf, const float* __restrict__ bf,
    const float* __restrict__ Wc, const float* __restrict__ bc,
    float* __restrict__ out)
{
    __shared__ float AsF[64 * GSA];
    __shared__ float AsC[64 * GSA];
    __shared__ float Bs[32 * GSB];
    const int Cin = 288;
    const int b = blockIdx.z, r0 = blockIdx.y * 64, n0 = blockIdx.x * 128;
    const int t = threadIdx.x, w = t >> 5, lane = t & 31;
    const int lr = lane >> 2, lc = lane & 3;
    const int wm = (w >> 2) * 32;   // 0 or 32
    const int wn = (w & 3) * 32;    // 0,32,64,96

    float accF[2][4][4], accC[2][4][4];
    #pragma unroll
    for (int mf = 0; mf < 2; mf++) {
        int rA = r0 + wm + mf * 16 + lr;
        float bf0 = bf[rA], bf1 = bf[rA + 8];
        float bc0 = bc[rA], bc1 = bc[rA + 8];
        #pragma unroll
        for (int nf = 0; nf < 4; nf++) {
            accF[mf][nf][0] = bf0; accF[mf][nf][1] = bf0;
            accF[mf][nf][2] = bf1; accF[mf][nf][3] = bf1;
            accC[mf][nf][0] = bc0; accC[mf][nf][1] = bc0;
            accC[mf][nf][2] = bc1; accC[mf][nf][3] = bc1;
        }
    }

    for (int k0 = 0; k0 < Cin; k0 += 32) {
        #pragma unroll
        for (int e = 0; e < 8; e++) {
            int idx = t + 256 * e;
            int r = idx >> 5, c = idx & 31;
            AsF[r * GSA + c] = __uint_as_float(f2tf(Wf[(size_t)(r0 + r) * Cin + k0 + c]));
            AsC[r * GSA + c] = __uint_as_float(f2tf(Wc[(size_t)(r0 + r) * Cin + k0 + c]));
        }
        #pragma unroll
        for (int e = 0; e < 16; e++) {
            int idx = t + 256 * e;
            int r = idx >> 7, c = idx & 127;
            Bs[r * GSB + c] = __uint_as_float(f2tf(load_in(x, extra, b, k0 + r, n0 + c)));
        }
        __syncthreads();

        #pragma unroll
        for (int kf = 0; kf < 4; kf++) {
            int kk = kf * 8;
            uint32_t aF[2][4], aC[2][4], bb[4][2];
            #pragma unroll
            for (int mf = 0; mf < 2; mf++) {
                int base = (wm + mf * 16 + lr) * GSA + kk + lc;
                aF[mf][0] = __float_as_uint(AsF[base]);
                aF[mf][1] = __float_as_uint(AsF[base + 8 * GSA]);
                aF[mf][2] = __float_as_uint(AsF[base + 4]);
                aF[mf][3] = __float_as_uint(AsF[base + 8 * GSA + 4]);
                aC[mf][0] = __float_as_uint(AsC[base]);
                aC[mf][1] = __float_as_uint(AsC[base + 8 * GSA]);
                aC[mf][2] = __float_as_uint(AsC[base + 4]);
                aC[mf][3] = __float_as_uint(AsC[base + 8 * GSA + 4]);
            }
            #pragma unroll
            for (int nf = 0; nf < 4; nf++) {
                int base = (kk + lc) * GSB + wn + nf * 8 + lr;
                bb[nf][0] = __float_as_uint(Bs[base]);
                bb[nf][1] = __float_as_uint(Bs[base + 4 * GSB]);
            }
            #pragma unroll
            for (int mf = 0; mf < 2; mf++)
                #pragma unroll
                for (int nf = 0; nf < 4; nf++) {
                    mma_tf32(accF[mf][nf][0], accF[mf][nf][1], accF[mf][nf][2], accF[mf][nf][3],
                             aF[mf][0], aF[mf][1], aF[mf][2], aF[mf][3], bb[nf][0], bb[nf][1]);
                    mma_tf32(accC[mf][nf][0], accC[mf][nf][1], accC[mf][nf][2], accC[mf][nf][3],
                             aC[mf][0], aC[mf][1], aC[mf][2], aC[mf][3], bb[nf][0], bb[nf][1]);
                }
        }
        __syncthreads();
    }

    // Epilogue: f*extra + relu(c)
    #pragma unroll
    for (int mf = 0; mf < 2; mf++) {
        int rA = r0 + wm + mf * 16 + lr;
        #pragma unroll
        for (int nf = 0; nf < 4; nf++) {
            int n = n0 + wn + nf * 8 + 2 * lc;
            #pragma unroll
            for (int h = 0; h < 2; h++) {
                int row = rA + h * 8;
                #pragma unroll
                for (int j = 0; j < 2; j++) {
                    float F = accF[mf][nf][2 * h + j];
                    float Cc = accC[mf][nf][2 * h + j];
                    float f = 1.0f / (1.0f + __expf(-F));
                    float cc = fmaxf(Cc, 0.0f);
                    size_t off = ((size_t)(b * 128 + row)) * 1024 + n + j;
                    out[off] = f * extra[off] + cc;
                }
            }
        }
    }
}

// ---------------------------------------------------------------------------
// q = tf32(relu(Wq @ [x|pos] + bq)) -> g_q      (Cin = 160)
// ---------------------------------------------------------------------------
__global__ __launch_bounds__(256) void q_kernel(
    const float* __restrict__ x, const float* __restrict__ Wq,
    const float* __restrict__ bq)
{
    __shared__ float As[64 * GSA];
    __shared__ float Bs[32 * GSB];
    const int Cin = 160;
    const int b = blockIdx.z, r0 = blockIdx.y * 64, n0 = blockIdx.x * 128;
    const int t = threadIdx.x, w = t >> 5, lane = t & 31;
    const int lr = lane >> 2, lc = lane & 3;
    const int wm = (w >> 2) * 32;
    const int wn = (w & 3) * 32;

    float acc[2][4][4];
    #pragma unroll
    for (int mf = 0; mf < 2; mf++) {
        int rA = r0 + wm + mf * 16 + lr;
        float b0 = bq[rA], b1 = bq[rA + 8];
        #pragma unroll
        for (int nf = 0; nf < 4; nf++) {
            acc[mf][nf][0] = b0; acc[mf][nf][1] = b0;
            acc[mf][nf][2] = b1; acc[mf][nf][3] = b1;
        }
    }

    for (int k0 = 0; k0 < Cin; k0 += 32) {
        #pragma unroll
        for (int e = 0; e < 8; e++) {
            int idx = t + 256 * e;
            int r = idx >> 5, c = idx & 31;
            As[r * GSA + c] = __uint_as_float(f2tf(Wq[(size_t)(r0 + r) * Cin + k0 + c]));
        }
        #pragma unroll
        for (int e = 0; e < 16; e++) {
            int idx = t + 256 * e;
            int r = idx >> 7, c = idx & 127;
            Bs[r * GSB + c] = __uint_as_float(f2tf(load_in(x, nullptr, b, k0 + r, n0 + c)));
        }
        __syncthreads();

        #pragma unroll
        for (int kf = 0; kf < 4; kf++) {
            int kk = kf * 8;
            uint32_t aa[2][4], bb[4][2];
            #pragma unroll
            for (int mf = 0; mf < 2; mf++) {
                int base = (wm + mf * 16 + lr) * GSA + kk + lc;
                aa[mf][0] = __float_as_uint(As[base]);
                aa[mf][1] = __float_as_uint(As[base + 8 * GSA]);
                aa[mf][2] = __float_as_uint(As[base + 4]);
                aa[mf][3] = __float_as_uint(As[base + 8 * GSA + 4]);
            }
            #pragma unroll
            for (int nf = 0; nf < 4; nf++) {
                int base = (kk + lc) * GSB + wn + nf * 8 + lr;
                bb[nf][0] = __float_as_uint(Bs[base]);
                bb[nf][1] = __float_as_uint(Bs[base + 4 * GSB]);
            }
            #pragma unroll
            for (int mf = 0; mf < 2; mf++)
                #pragma unroll
                for (int nf = 0; nf < 4; nf++)
                    mma_tf32(acc[mf][nf][0], acc[mf][nf][1], acc[mf][nf][2], acc[mf][nf][3],
                             aa[mf][0], aa[mf][1], aa[mf][2], aa[mf][3], bb[nf][0], bb[nf][1]);
        }
        __syncthreads();
    }

    #pragma unroll
    for (int mf = 0; mf < 2; mf++) {
        int rA = r0 + wm + mf * 16 + lr;
        #pragma unroll
        for (int nf = 0; nf < 4; nf++) {
            int n = n0 + wn + nf * 8 + 2 * lc;
            #pragma unroll
            for (int h = 0; h < 2; h++) {
                int row = rA + h * 8;
                #pragma unroll
                for (int j = 0; j < 2; j++) {
                    float val = fmaxf(acc[mf][nf][2 * h + j], 0.0f);
                    g_q[((size_t)(b * 128 + row)) * 1024 + n + j] =
                        __uint_as_float(f2tf(val));
                }
            }
        }
    }
}

// ---------------------------------------------------------------------------
// Causal attention, tensor-core flash style.
// Block: 64 queries, all 128 v-channels. 8 warps: warpM=w>>1 (16 q rows),
// warpN=w&1 (32 keys for S / 64 v-channels for PV).
// ---------------------------------------------------------------------------
#define SQ 132   // Qt[i][c] stride (128+4)
#define SK 72    // Ks[c][m] stride (64+8)
#define SV 68    // Vs[v][m] stride (64+4)
#define SP 68    // Ps[i][m] stride (64+4)

#define OFF_QT 0
#define OFF_KS (64 * SQ)                 // 8448
#define OFF_VS (OFF_KS + 128 * SK)       // 17664
#define OFF_PS (OFF_VS + 128 * SV)       // 26368
#define OFF_MAX (OFF_PS + 64 * SP)       // 30720
#define OFF_SUM (OFF_MAX + 64)
#define OFF_ALP (OFF_SUM + 64)
#define ATTN_SMEM_FLOATS (OFF_ALP + 64)  // 30912
#define ATTN_SMEM_BYTES (ATTN_SMEM_FLOATS * 4)

__global__ __launch_bounds__(256) void attn_kernel(
    const float* __restrict__ k, const float* __restrict__ v,
    float* __restrict__ out)
{
    extern __shared__ float sm[];
    float* Qt = sm + OFF_QT;
    float* Ks = sm + OFF_KS;
    float* Vs = sm + OFF_VS;
    float* Ps = sm + OFF_PS;
    float* sMax = sm + OFF_MAX;
    float* sSum = sm + OFF_SUM;
    float* sAlpha = sm + OFF_ALP;

    const int b = blockIdx.y;
    const int bx = 15 - blockIdx.x;      // heavy blocks first
    const int n0 = bx * 64;
    const int t = threadIdx.x, w = t >> 5, lane = t & 31;
    const int lr = lane >> 2, lc = lane & 3;
    const int wm = (w >> 1) * 16;        // 16 query rows per warp
    const int wn2 = (w & 1);             // 0/1
    const float scale = 0.08838834764831845f;

    // Stage Q tile transposed: Qt[i][c] (already tf32 in g_q)
    #pragma unroll
    for (int e = 0; e < 32; e++) {
        int idx = t + 256 * e;
        int c = idx >> 6, i = idx & 63;
        Qt[i * SQ + c] = g_q[((size_t)(b * 128 + c)) * 1024 + n0 + i];
    }
    if (t < 64) { sMax[t] = -1e30f; sSum[t] = 0.0f; }

    float O[8][4];
    #pragma unroll
    for (int nf = 0; nf < 8; nf++)
        #pragma unroll
        for (int j = 0; j < 4; j++) O[nf][j] = 0.0f;

    for (int mt = 0; mt <= bx; mt++) {
        const int m0 = mt * 64;
        #pragma unroll
        for (int e = 0; e < 32; e++) {
            int idx = t + 256 * e;
            int c = idx >> 6, m = idx & 63;
            Ks[c * SK + m] = __uint_as_float(f2tf(k[((size_t)(b * 128 + c)) * 1024 + m0 + m]));
            Vs[c * SV + m] = __uint_as_float(f2tf(v[((size_t)(b * 128 + c)) * 1024 + m0 + m]));
        }
        __syncthreads();

        // ---- S = Q^T K (64x64, contract over 128 channels) ----
        float S[4][4];
        #pragma unroll
        for (int nf = 0; nf < 4; nf++)
            #pragma unroll
            for (int j = 0; j < 4; j++) S[nf][j] = 0.0f;

        #pragma unroll
        for (int kf = 0; kf < 16; kf++) {
            int kc = kf * 8;
            int abase = (wm + lr) * SQ + kc + lc;
            uint32_t a0 = __float_as_uint(Qt[abase]);
            uint32_t a1 = __float_as_uint(Qt[abase + 8 * SQ]);
            uint32_t a2 = __float_as_uint(Qt[abase + 4]);
            uint32_t a3 = __float_as_uint(Qt[abase + 8 * SQ + 4]);
            #pragma unroll
            for (int nf = 0; nf < 4; nf++) {
                int bbase = (kc + lc) * SK + wn2 * 32 + nf * 8 + lr;
                uint32_t b0 = __float_as_uint(Ks[bbase]);
                uint32_t b1 = __float_as_uint(Ks[bbase + 4 * SK]);
                mma_tf32(S[nf][0], S[nf][1], S[nf][2], S[nf][3], a0, a1, a2, a3, b0, b1);
            }
        }
        // Store scaled scores
        #pragma unroll
        for (int nf = 0; nf < 4; nf++) {
            int col = wn2 * 32 + nf * 8 + 2 * lc;
            int row = wm + lr;
            Ps[row * SP + col]           = S[nf][0] * scale;
            Ps[row * SP + col + 1]       = S[nf][1] * scale;
            Ps[(row + 8) * SP + col]     = S[nf][2] * scale;
            Ps[(row + 8) * SP + col + 1] = S[nf][3] * scale;
        }
        __syncthreads();

        // ---- Online softmax: 4 threads per row ----
        {
            int r = t >> 2, qd = t & 3;
            bool diag = (mt == bx);
            float vals[16];
            float tm = -1e30f;
            #pragma unroll
            for (int j = 0; j < 16; j++) {
                int m = qd * 16 + j;
                float s = Ps[r * SP + m];
                if (diag && m > r) s = -1e30f;
                vals[j] = s;
                tm = fmaxf(tm, s);
            }
            tm = fmaxf(tm, __shfl_xor_sync(0xffffffffu, tm, 1));
            tm = fmaxf(tm, __shfl_xor_sync(0xffffffffu, tm, 2));
            float rm = sMax[r];
            float nm = fmaxf(rm, tm);
            float ps = 0.0f;
            #pragma unroll
            for (int j = 0; j < 16; j++) {
                float p = __uint_as_float(f2tf(__expf(vals[j] - nm)));
                Ps[r * SP + qd * 16 + j] = p;
                ps += p;
            }
            ps += __shfl_xor_sync(0xffffffffu, ps, 1);
            ps += __shfl_xor_sync(0xffffffffu, ps, 2);
            float alpha = __expf(rm - nm);
            if (qd == 0) {
                sSum[r] = sSum[r] * alpha + ps;
                sMax[r] = nm;
                sAlpha[r] = alpha;
            }
        }
        __syncthreads();

        // ---- O = O*alpha + P @ V^T ----
        float aLo = sAlpha[wm + lr], aHi = sAlpha[wm + lr + 8];
        #pragma unroll
        for (int nf = 0; nf < 8; nf++) {
            O[nf][0] *= aLo; O[nf][1] *= aLo;
            O[nf][2] *= aHi; O[nf][3] *= aHi;
        }
        #pragma unroll
        for (int kf = 0; kf < 8; kf++) {
            int kc = kf * 8;
            int abase = (wm + lr) * SP + kc + lc;
            uint32_t a0 = __float_as_uint(Ps[abase]);
            uint32_t a1 = __float_as_uint(Ps[abase + 8 * SP]);
            uint32_t a2 = __float_as_uint(Ps[abase + 4]);
            uint32_t a3 = __float_as_uint(Ps[abase + 8 * SP + 4]);
            #pragma unroll
            for (int nf = 0; nf < 8; nf++) {
                int vb = wn2 * 64 + nf * 8 + lr;
                int bbase = vb * SV + kc + lc;
                uint32_t b0 = __float_as_uint(Vs[bbase]);
                uint32_t b1 = __float_as_uint(Vs[bbase + 4]);
                mma_tf32(O[nf][0], O[nf][1], O[nf][2], O[nf][3], a0, a1, a2, a3, b0, b1);
            }
        }
        __syncthreads();
    }

    // Normalize and store
    float invLo = 1.0f / sSum[wm + lr];
    float invHi = 1.0f / sSum[wm + lr + 8];
    int nLo = n0 + wm + lr, nHi = nLo + 8;
    #pragma unroll
    for (int nf = 0; nf < 8; nf++) {
        int vc = wn2 * 64 + nf * 8 + 2 * lc;
        out[((size_t)(b * 128 + vc))     * 1024 + nLo] = O[nf][0] * invLo;
        out[((size_t)(b * 128 + vc + 1)) * 1024 + nLo] = O[nf][1] * invLo;
        out[((size_t)(b * 128 + vc))     * 1024 + nHi] = O[nf][2] * invHi;
        out[((size_t)(b * 128 + vc + 1)) * 1024 + nHi] = O[nf][3] * invHi;
    }
}

// ---------------------------------------------------------------------------
// Launch
// ---------------------------------------------------------------------------
extern "C" void kernel_launch(void* const* d_in, const int* in_sizes, int n_in,
                              void* d_out, int out_size)
{
    const float* x   = (const float*)d_in[0];
    const float* k   = (const float*)d_in[1];
    const float* v   = (const float*)d_in[2];
    const float* Wq  = (const float*)d_in[3];
    const float* bq  = (const float*)d_in[4];
    const float* Wfk = (const float*)d_in[5];
    const float* bfk = (const float*)d_in[6];
    const float* Wck = (const float*)d_in[7];
    const float* bck = (const float*)d_in[8];
    const float* Wfv = (const float*)d_in[9];
    const float* bfv = (const float*)d_in[10];
    const float* Wcv = (const float*)d_in[11];
    const float* bcv = (const float*)d_in[12];

    float* out2 = (float*)d_out;
    float* kn   = out2 + (size_t)32 * 128 * 1024;
    float* vn   = kn   + (size_t)32 * 128 * 1024;

    pos_kernel<<<32, 1024>>>();
    q_kernel<<<dim3(8, 2, 32), 256>>>(x, Wq, bq);
    gated_kernel<<<dim3(8, 2, 32), 256>>>(x, k, Wfk, bfk, Wck, bck, kn);
    gated_kernel<<<dim3(8, 2, 32), 256>>>(x, v, Wfv, bfv, Wcv, bcv, vn);

    cudaFuncSetAttribute(attn_kernel,
                         cudaFuncAttributeMaxDynamicSharedMemorySize,
                         ATTN_SMEM_BYTES);
    attn_kernel<<<dim3(16, 32), 256, ATTN_SMEM_BYTES>>>(k, v, out2);
}

// round 3
// speedup vs baseline: 3.2377x; 2.6039x over previous
#include <cuda_runtime.h>
#include <math.h>
#include <stdint.h>

// ---------------------------------------------------------------------------
// Scratch (__device__ globals; no allocation allowed)
// ---------------------------------------------------------------------------
__device__ float g_pos[32 * 1024];              // [32 ch][1024], fp32
__device__ float g_x0[32 * 160 * 1024];         // tf32 [B][160][N]  (x|pos)
__device__ float g_kc[32 * 128 * 1024];         // tf32 k
__device__ float g_vc[32 * 128 * 1024];         // tf32 v
__device__ float g_q [32 * 128 * 1024];         // tf32 q
__device__ float g_Wq [128 * 160];              // tf32 weights
__device__ float g_Wfk[128 * 288];
__device__ float g_Wck[128 * 288];
__device__ float g_Wfv[128 * 288];
__device__ float g_Wcv[128 * 288];

// ---------------------------------------------------------------------------
// Helpers
// ---------------------------------------------------------------------------
__device__ __forceinline__ uint32_t f2tf(float x) {
    uint32_t u;
    asm("cvt.rna.tf32.f32 %0, %1;" : "=r"(u) : "f"(x));
    return u;
}
__device__ __forceinline__ float f2tff(float x) { return __uint_as_float(f2tf(x)); }

__device__ __forceinline__ void mma_tf32(
    float& d0, float& d1, float& d2, float& d3,
    uint32_t a0, uint32_t a1, uint32_t a2, uint32_t a3,
    uint32_t b0, uint32_t b1)
{
    asm volatile(
        "mma.sync.aligned.m16n8k8.row.col.f32.tf32.tf32.f32 "
        "{%0,%1,%2,%3}, {%4,%5,%6,%7}, {%8,%9}, {%0,%1,%2,%3};"
        : "+f"(d0), "+f"(d1), "+f"(d2), "+f"(d3)
        : "r"(a0), "r"(a1), "r"(a2), "r"(a3), "r"(b0), "r"(b1));
}

__device__ __forceinline__ void cpa16(uint32_t dst, const void* src) {
    asm volatile("cp.async.ca.shared.global [%0], [%1], 16;" :: "r"(dst), "l"(src));
}
#define CP_COMMIT() asm volatile("cp.async.commit_group;" ::: "memory")

// ---------------------------------------------------------------------------
// Positional embedding (faithful to numpy .view reinterpret)
// ---------------------------------------------------------------------------
__global__ void pos_kernel() {
    int idx = blockIdx.x * blockDim.x + threadIdx.x;
    if (idx >= 32 * 1024) return;
    int c = idx >> 10, n = idx & 1023;
    int y = n >> 5, x = n & 31;
    int i = (c < 16) ? (c * 32 + y) : ((c - 16) * 32 + x);
    int p = i >> 4, j = i & 15;
    float r = 0.0f;
    if (p != 0) {
        double denom = pow(10000.0, (double)(2 * (j >> 1)) / 16.0);
        double val = (double)p / denom;
        r = (j & 1) ? (float)cos(val) : (float)sin(val);
    }
    g_pos[idx] = r;
}

// ---------------------------------------------------------------------------
// Pack kernel: tf32-round x|pos -> g_x0, k -> g_kc, v -> g_vc  (float4)
// ---------------------------------------------------------------------------
__device__ __forceinline__ float4 tf4(float4 s) {
    s.x = f2tff(s.x); s.y = f2tff(s.y); s.z = f2tff(s.z); s.w = f2tff(s.w);
    return s;
}

__global__ void pack_kernel(const float* __restrict__ x,
                            const float* __restrict__ k,
                            const float* __restrict__ v)
{
    const int NX0 = 32 * 160 * 256;   // float4 counts
    const int NKV = 32 * 128 * 256;
    int i = blockIdx.x * blockDim.x + threadIdx.x;
    if (i < NX0) {
        int n4 = i & 255;
        int cb = i >> 8;
        int c = cb % 160, b = cb / 160;
        float4 s;
        if (c < 128)
            s = ((const float4*)x)[(size_t)(b * 128 + c) * 256 + n4];
        else
            s = ((const float4*)g_pos)[(c - 128) * 256 + n4];
        ((float4*)g_x0)[i] = tf4(s);
    } else if (i < NX0 + NKV) {
        int j = i - NX0;
        ((float4*)g_kc)[j] = tf4(((const float4*)k)[j]);
    } else if (i < NX0 + 2 * NKV) {
        int j = i - NX0 - NKV;
        ((float4*)g_vc)[j] = tf4(((const float4*)v)[j]);
    }
}

__global__ void wpack_kernel(const float* __restrict__ Wq,
                             const float* __restrict__ Wfk, const float* __restrict__ Wck,
                             const float* __restrict__ Wfv, const float* __restrict__ Wcv)
{
    int i = blockIdx.x * blockDim.x + threadIdx.x;
    if (i < 128 * 160) g_Wq[i] = f2tff(Wq[i]);
    if (i < 128 * 288) {
        g_Wfk[i] = f2tff(Wfk[i]);
        g_Wck[i] = f2tff(Wck[i]);
        g_Wfv[i] = f2tff(Wfv[i]);
        g_Wcv[i] = f2tff(Wcv[i]);
    }
}

// ---------------------------------------------------------------------------
// Gated highway update, both gates in one grid (z = b*2 + which).
// CTA: 64 out-rows x 128 cols, K=288 in 9 steps, cp.async double-buffered.
// ---------------------------------------------------------------------------
#define GSA 36          // A smem row stride (words); 36 % 32 == 4
#define GSB 136         // B smem row stride; 136 % 32 == 8
#define GBUF 8960       // floats per pipeline buffer (2*64*GSA + 32*GSB)
#define GSMEM_BYTES (2 * GBUF * 4)

__global__ __launch_bounds__(256, 2) void gated_kernel(
    const float* __restrict__ kOrig, const float* __restrict__ vOrig,
    const float* __restrict__ bfk, const float* __restrict__ bck,
    const float* __restrict__ bfv, const float* __restrict__ bcv,
    float* __restrict__ outk, float* __restrict__ outv)
{
    extern __shared__ float sm[];
    const int z = blockIdx.z, b = z >> 1, which = z & 1;
    const float* Wf   = which ? g_Wfv : g_Wfk;
    const float* Wc   = which ? g_Wcv : g_Wck;
    const float* bfp  = which ? bfv : bfk;
    const float* bcp  = which ? bcv : bck;
    const float* extc = which ? g_vc : g_kc;
    const float* extra = which ? vOrig : kOrig;
    float* out = which ? outv : outk;

    const int r0 = blockIdx.y * 64, n0 = blockIdx.x * 128;
    const int t = threadIdx.x, w = t >> 5, lane = t & 31;
    const int lr = lane >> 2, lc = lane & 3;
    const int wm = (w >> 2) * 32;   // 0 / 32
    const int wn = (w & 3) * 32;    // 0,32,64,96
    const uint32_t sbase = (uint32_t)__cvta_generic_to_shared(sm);

    float accF[2][4][4], accC[2][4][4];
    #pragma unroll
    for (int mf = 0; mf < 2; mf++) {
        int rA = r0 + wm + mf * 16 + lr;
        float bf0 = bfp[rA], bf1 = bfp[rA + 8];
        float bc0 = bcp[rA], bc1 = bcp[rA + 8];
        #pragma unroll
        for (int nf = 0; nf < 4; nf++) {
            accF[mf][nf][0] = bf0; accF[mf][nf][1] = bf0;
            accF[mf][nf][2] = bf1; accF[mf][nf][3] = bf1;
            accC[mf][nf][0] = bc0; accC[mf][nf][1] = bc0;
            accC[mf][nf][2] = bc1; accC[mf][nf][3] = bc1;
        }
    }

    auto issue = [&](int it, int buf) {
        const int k0 = it * 32;
        const uint32_t base = sbase + buf * (GBUF * 4);
        #pragma unroll
        for (int h = 0; h < 2; h++) {
            int a = t + 256 * h;                // 0..511
            int r = a >> 3, c4 = a & 7;
            cpa16(base + (r * GSA + c4 * 4) * 4,
                  Wf + (size_t)(r0 + r) * 288 + k0 + c4 * 4);
            cpa16(base + (2304 + r * GSA + c4 * 4) * 4,
                  Wc + (size_t)(r0 + r) * 288 + k0 + c4 * 4);
        }
        #pragma unroll
        for (int h = 0; h < 4; h++) {
            int bi = t + 256 * h;               // 0..1023
            int r = bi >> 5, c4 = bi & 31;
            int row = k0 + r;
            const float* src = (row < 160)
                ? (g_x0 + ((size_t)b * 160 + row) * 1024 + n0 + c4 * 4)
                : (extc + ((size_t)b * 128 + (row - 160)) * 1024 + n0 + c4 * 4);
            cpa16(base + (4608 + r * GSB + c4 * 4) * 4, src);
        }
        CP_COMMIT();
    };

    issue(0, 0);
    #pragma unroll 1
    for (int it = 0; it < 9; it++) {
        if (it < 8) {
            issue(it + 1, (it + 1) & 1);
            asm volatile("cp.async.wait_group 1;" ::: "memory");
        } else {
            asm volatile("cp.async.wait_group 0;" ::: "memory");
        }
        __syncthreads();

        const float* AsF = sm + (it & 1) * GBUF;
        const float* AsC = AsF + 2304;
        const float* Bs  = AsF + 4608;

        #pragma unroll
        for (int kf = 0; kf < 4; kf++) {
            int kk = kf * 8;
            uint32_t aF[2][4], aC[2][4], bb[4][2];
            #pragma unroll
            for (int mf = 0; mf < 2; mf++) {
                int base = (wm + mf * 16 + lr) * GSA + kk + lc;
                aF[mf][0] = __float_as_uint(AsF[base]);
                aF[mf][1] = __float_as_uint(AsF[base + 8 * GSA]);
                aF[mf][2] = __float_as_uint(AsF[base + 4]);
                aF[mf][3] = __float_as_uint(AsF[base + 8 * GSA + 4]);
                aC[mf][0] = __float_as_uint(AsC[base]);
                aC[mf][1] = __float_as_uint(AsC[base + 8 * GSA]);
                aC[mf][2] = __float_as_uint(AsC[base + 4]);
                aC[mf][3] = __float_as_uint(AsC[base + 8 * GSA + 4]);
            }
            #pragma unroll
            for (int nf = 0; nf < 4; nf++) {
                int base = (kk + lc) * GSB + wn + nf * 8 + lr;
                bb[nf][0] = __float_as_uint(Bs[base]);
                bb[nf][1] = __float_as_uint(Bs[base + 4 * GSB]);
            }
            #pragma unroll
            for (int mf = 0; mf < 2; mf++)
                #pragma unroll
                for (int nf = 0; nf < 4; nf++) {
                    mma_tf32(accF[mf][nf][0], accF[mf][nf][1], accF[mf][nf][2], accF[mf][nf][3],
                             aF[mf][0], aF[mf][1], aF[mf][2], aF[mf][3], bb[nf][0], bb[nf][1]);
                    mma_tf32(accC[mf][nf][0], accC[mf][nf][1], accC[mf][nf][2], accC[mf][nf][3],
                             aC[mf][0], aC[mf][1], aC[mf][2], aC[mf][3], bb[nf][0], bb[nf][1]);
                }
        }
        __syncthreads();
    }

    // Epilogue: sigmoid(F)*extra + relu(C)
    #pragma unroll
    for (int mf = 0; mf < 2; mf++) {
        int rA = r0 + wm + mf * 16 + lr;
        #pragma unroll
        for (int nf = 0; nf < 4; nf++) {
            int n = n0 + wn + nf * 8 + 2 * lc;
            #pragma unroll
            for (int h = 0; h < 2; h++) {
                int row = rA + h * 8;
                #pragma unroll
                for (int j = 0; j < 2; j++) {
                    float F  = accF[mf][nf][2 * h + j];
                    float Cc = accC[mf][nf][2 * h + j];
                    float f  = 1.0f / (1.0f + __expf(-F));
                    float cc = fmaxf(Cc, 0.0f);
                    size_t off = ((size_t)(b * 128 + row)) * 1024 + n + j;
                    out[off] = f * extra[off] + cc;
                }
            }
        }
    }
}

// ---------------------------------------------------------------------------
// q = tf32(relu(Wq @ x0 + bq)) -> g_q     (Cin=160, 5 k-steps)
// ---------------------------------------------------------------------------
#define QBUF 6656
#define QSMEM_BYTES (2 * QBUF * 4)

__global__ __launch_bounds__(256, 2) void q_kernel(const float* __restrict__ bq)
{
    extern __shared__ float sm[];
    const int b = blockIdx.z, r0 = blockIdx.y * 64, n0 = blockIdx.x * 128;
    const int t = threadIdx.x, w = t >> 5, lane = t & 31;
    const int lr = lane >> 2, lc = lane & 3;
    const int wm = (w >> 2) * 32;
    const int wn = (w & 3) * 32;
    const uint32_t sbase = (uint32_t)__cvta_generic_to_shared(sm);

    float acc[2][4][4];
    #pragma unroll
    for (int mf = 0; mf < 2; mf++) {
        int rA = r0 + wm + mf * 16 + lr;
        float b0 = bq[rA], b1 = bq[rA + 8];
        #pragma unroll
        for (int nf = 0; nf < 4; nf++) {
            acc[mf][nf][0] = b0; acc[mf][nf][1] = b0;
            acc[mf][nf][2] = b1; acc[mf][nf][3] = b1;
        }
    }

    auto issue = [&](int it, int buf) {
        const int k0 = it * 32;
        const uint32_t base = sbase + buf * (QBUF * 4);
        #pragma unroll
        for (int h = 0; h < 2; h++) {
            int a = t + 256 * h;
            int r = a >> 3, c4 = a & 7;
            cpa16(base + (r * GSA + c4 * 4) * 4,
                  g_Wq + (size_t)(r0 + r) * 160 + k0 + c4 * 4);
        }
        #pragma unroll
        for (int h = 0; h < 4; h++) {
            int bi = t + 256 * h;
            int r = bi >> 5, c4 = bi & 31;
            cpa16(base + (2304 + r * GSB + c4 * 4) * 4,
                  g_x0 + ((size_t)b * 160 + k0 + r) * 1024 + n0 + c4 * 4);
        }
        CP_COMMIT();
    };

    issue(0, 0);
    #pragma unroll 1
    for (int it = 0; it < 5; it++) {
        if (it < 4) {
            issue(it + 1, (it + 1) & 1);
            asm volatile("cp.async.wait_group 1;" ::: "memory");
        } else {
            asm volatile("cp.async.wait_group 0;" ::: "memory");
        }
        __syncthreads();

        const float* As = sm + (it & 1) * QBUF;
        const float* Bs = As + 2304;

        #pragma unroll
        for (int kf = 0; kf < 4; kf++) {
            int kk = kf * 8;
            uint32_t aa[2][4], bb[4][2];
            #pragma unroll
            for (int mf = 0; mf < 2; mf++) {
                int base = (wm + mf * 16 + lr) * GSA + kk + lc;
                aa[mf][0] = __float_as_uint(As[base]);
                aa[mf][1] = __float_as_uint(As[base + 8 * GSA]);
                aa[mf][2] = __float_as_uint(As[base + 4]);
                aa[mf][3] = __float_as_uint(As[base + 8 * GSA + 4]);
            }
            #pragma unroll
            for (int nf = 0; nf < 4; nf++) {
                int base = (kk + lc) * GSB + wn + nf * 8 + lr;
                bb[nf][0] = __float_as_uint(Bs[base]);
                bb[nf][1] = __float_as_uint(Bs[base + 4 * GSB]);
            }
            #pragma unroll
            for (int mf = 0; mf < 2; mf++)
                #pragma unroll
                for (int nf = 0; nf < 4; nf++)
                    mma_tf32(acc[mf][nf][0], acc[mf][nf][1], acc[mf][nf][2], acc[mf][nf][3],
                             aa[mf][0], aa[mf][1], aa[mf][2], aa[mf][3], bb[nf][0], bb[nf][1]);
        }
        __syncthreads();
    }

    #pragma unroll
    for (int mf = 0; mf < 2; mf++) {
        int rA = r0 + wm + mf * 16 + lr;
        #pragma unroll
        for (int nf = 0; nf < 4; nf++) {
            int n = n0 + wn + nf * 8 + 2 * lc;
            #pragma unroll
            for (int h = 0; h < 2; h++) {
                int row = rA + h * 8;
                #pragma unroll
                for (int j = 0; j < 2; j++) {
                    float val = fmaxf(acc[mf][nf][2 * h + j], 0.0f);
                    g_q[((size_t)(b * 128 + row)) * 1024 + n + j] = f2tff(val);
                }
            }
        }
    }
}

// ---------------------------------------------------------------------------
// Causal attention (flash style, tensor core), cp.async double-buffered K/V.
// ---------------------------------------------------------------------------
#define SQ 132
#define SK 72
#define SV 68
#define SP 68

#define OFF_QT 0
#define OFF_KS 8448                       // 2 bufs x 128*72
#define OFF_VS (OFF_KS + 2 * 128 * SK)    // 26880
#define OFF_PS (OFF_VS + 2 * 128 * SV)    // 44288
#define OFF_MAX (OFF_PS + 64 * SP)        // 48640
#define OFF_SUM (OFF_MAX + 64)
#define OFF_ALP (OFF_SUM + 64)
#define ATTN_SMEM_FLOATS (OFF_ALP + 64)   // 48832
#define ATTN_SMEM_BYTES (ATTN_SMEM_FLOATS * 4)

__global__ __launch_bounds__(256) void attn_kernel(float* __restrict__ out)
{
    extern __shared__ float sm[];
    float* Qt = sm + OFF_QT;
    float* Ps = sm + OFF_PS;
    float* sMax = sm + OFF_MAX;
    float* sSum = sm + OFF_SUM;
    float* sAlpha = sm + OFF_ALP;

    const int b = blockIdx.y;
    const int bx = 15 - blockIdx.x;       // heavy blocks first
    const int n0 = bx * 64;
    const int t = threadIdx.x, w = t >> 5, lane = t & 31;
    const int lr = lane >> 2, lc = lane & 3;
    const int wm = (w >> 1) * 16;
    const int wn2 = (w & 1);
    const float scale = 0.08838834764831845f;
    const uint32_t sbase = (uint32_t)__cvta_generic_to_shared(sm);

    // Q tile transposed (g_q already tf32)
    #pragma unroll
    for (int e = 0; e < 32; e++) {
        int idx = t + 256 * e;
        int c = idx >> 6, i = idx & 63;
        Qt[i * SQ + c] = g_q[((size_t)(b * 128 + c)) * 1024 + n0 + i];
    }
    if (t < 64) { sMax[t] = -1e30f; sSum[t] = 0.0f; }

    auto issue_kv = [&](int mt, int p) {
        const int m0 = mt * 64;
        const uint32_t kb = sbase + (OFF_KS + p * 128 * SK) * 4;
        const uint32_t vb = sbase + (OFF_VS + p * 128 * SV) * 4;
        #pragma unroll
        for (int h = 0; h < 8; h++) {
            int idx = t + 256 * h;            // 0..2047
            int c = idx >> 4, m4 = idx & 15;
            cpa16(kb + (c * SK + m4 * 4) * 4,
                  g_kc + ((size_t)(b * 128 + c)) * 1024 + m0 + m4 * 4);
            cpa16(vb + (c * SV + m4 * 4) * 4,
                  g_vc + ((size_t)(b * 128 + c)) * 1024 + m0 + m4 * 4);
        }
        CP_COMMIT();
    };

    float O[8][4];
    #pragma unroll
    for (int nf = 0; nf < 8; nf++)
        #pragma unroll
        for (int j = 0; j < 4; j++) O[nf][j] = 0.0f;

    issue_kv(0, 0);
    #pragma unroll 1
    for (int mt = 0; mt <= bx; mt++) {
        if (mt < bx) {
            issue_kv(mt + 1, (mt + 1) & 1);
            asm volatile("cp.async.wait_group 1;" ::: "memory");
        } else {
            asm volatile("cp.async.wait_group 0;" ::: "memory");
        }
        __syncthreads();

        const float* Ks = sm + OFF_KS + (mt & 1) * 128 * SK;
        const float* Vs = sm + OFF_VS + (mt & 1) * 128 * SV;

        // ---- S = Q^T K ----
        float S[4][4];
        #pragma unroll
        for (int nf = 0; nf < 4; nf++)
            #pragma unroll
            for (int j = 0; j < 4; j++) S[nf][j] = 0.0f;

        #pragma unroll
        for (int kf = 0; kf < 16; kf++) {
            int kc = kf * 8;
            int abase = (wm + lr) * SQ + kc + lc;
            uint32_t a0 = __float_as_uint(Qt[abase]);
            uint32_t a1 = __float_as_uint(Qt[abase + 8 * SQ]);
            uint32_t a2 = __float_as_uint(Qt[abase + 4]);
            uint32_t a3 = __float_as_uint(Qt[abase + 8 * SQ + 4]);
            #pragma unroll
            for (int nf = 0; nf < 4; nf++) {
                int bbase = (kc + lc) * SK + wn2 * 32 + nf * 8 + lr;
                uint32_t b0 = __float_as_uint(Ks[bbase]);
                uint32_t b1 = __float_as_uint(Ks[bbase + 4 * SK]);
                mma_tf32(S[nf][0], S[nf][1], S[nf][2], S[nf][3], a0, a1, a2, a3, b0, b1);
            }
        }
        #pragma unroll
        for (int nf = 0; nf < 4; nf++) {
            int col = wn2 * 32 + nf * 8 + 2 * lc;
            int row = wm + lr;
            Ps[row * SP + col]           = S[nf][0] * scale;
            Ps[row * SP + col + 1]       = S[nf][1] * scale;
            Ps[(row + 8) * SP + col]     = S[nf][2] * scale;
            Ps[(row + 8) * SP + col + 1] = S[nf][3] * scale;
        }
        __syncthreads();

        // ---- Online softmax: 4 threads per row ----
        {
            int r = t >> 2, qd = t & 3;
            bool diag = (mt == bx);
            float vals[16];
            float tm = -1e30f;
            #pragma unroll
            for (int j = 0; j < 16; j++) {
                int m = qd * 16 + j;
                float s = Ps[r * SP + m];
                if (diag && m > r) s = -1e30f;
                vals[j] = s;
                tm = fmaxf(tm, s);
            }
            tm = fmaxf(tm, __shfl_xor_sync(0xffffffffu, tm, 1));
            tm = fmaxf(tm, __shfl_xor_sync(0xffffffffu, tm, 2));
            float rm = sMax[r];
            float nm = fmaxf(rm, tm);
            float ps = 0.0f;
            #pragma unroll
            for (int j = 0; j < 16; j++) {
                float p = f2tff(__expf(vals[j] - nm));
                Ps[r * SP + qd * 16 + j] = p;
                ps += p;
            }
            ps += __shfl_xor_sync(0xffffffffu, ps, 1);
            ps += __shfl_xor_sync(0xffffffffu, ps, 2);
            float alpha = __expf(rm - nm);
            if (qd == 0) {
                sSum[r] = sSum[r] * alpha + ps;
                sMax[r] = nm;
                sAlpha[r] = alpha;
            }
        }
        __syncthreads();

        // ---- O = O*alpha + P @ V^T ----
        float aLo = sAlpha[wm + lr], aHi = sAlpha[wm + lr + 8];
        #pragma unroll
        for (int nf = 0; nf < 8; nf++) {
            O[nf][0] *= aLo; O[nf][1] *= aLo;
            O[nf][2] *= aHi; O[nf][3] *= aHi;
        }
        #pragma unroll
        for (int kf = 0; kf < 8; kf++) {
            int kc = kf * 8;
            int abase = (wm + lr) * SP + kc + lc;
            uint32_t a0 = __float_as_uint(Ps[abase]);
            uint32_t a1 = __float_as_uint(Ps[abase + 8 * SP]);
            uint32_t a2 = __float_as_uint(Ps[abase + 4]);
            uint32_t a3 = __float_as_uint(Ps[abase + 8 * SP + 4]);
            #pragma unroll
            for (int nf = 0; nf < 8; nf++) {
                int vb = wn2 * 64 + nf * 8 + lr;
                int bbase = vb * SV + kc + lc;
                uint32_t b0 = __float_as_uint(Vs[bbase]);
                uint32_t b1 = __float_as_uint(Vs[bbase + 4]);
                mma_tf32(O[nf][0], O[nf][1], O[nf][2], O[nf][3], a0, a1, a2, a3, b0, b1);
            }
        }
        __syncthreads();
    }

    float invLo = 1.0f / sSum[wm + lr];
    float invHi = 1.0f / sSum[wm + lr + 8];
    int nLo = n0 + wm + lr, nHi = nLo + 8;
    #pragma unroll
    for (int nf = 0; nf < 8; nf++) {
        int vc = wn2 * 64 + nf * 8 + 2 * lc;
        out[((size_t)(b * 128 + vc))     * 1024 + nLo] = O[nf][0] * invLo;
        out[((size_t)(b * 128 + vc + 1)) * 1024 + nLo] = O[nf][1] * invLo;
        out[((size_t)(b * 128 + vc))     * 1024 + nHi] = O[nf][2] * invHi;
        out[((size_t)(b * 128 + vc + 1)) * 1024 + nHi] = O[nf][3] * invHi;
    }
}

// ---------------------------------------------------------------------------
// Launch
// ---------------------------------------------------------------------------
extern "C" void kernel_launch(void* const* d_in, const int* in_sizes, int n_in,
                              void* d_out, int out_size)
{
    const float* x   = (const float*)d_in[0];
    const float* k   = (const float*)d_in[1];
    const float* v   = (const float*)d_in[2];
    const float* Wq  = (const float*)d_in[3];
    const float* bq  = (const float*)d_in[4];
    const float* Wfk = (const float*)d_in[5];
    const float* bfk = (const float*)d_in[6];
    const float* Wck = (const float*)d_in[7];
    const float* bck = (const float*)d_in[8];
    const float* Wfv = (const float*)d_in[9];
    const float* bfv = (const float*)d_in[10];
    const float* Wcv = (const float*)d_in[11];
    const float* bcv = (const float*)d_in[12];

    float* out2 = (float*)d_out;
    float* kn   = out2 + (size_t)32 * 128 * 1024;
    float* vn   = kn   + (size_t)32 * 128 * 1024;

    static bool attr_done = false;
    if (!attr_done) {
        cudaFuncSetAttribute(gated_kernel, cudaFuncAttributeMaxDynamicSharedMemorySize, GSMEM_BYTES);
        cudaFuncSetAttribute(q_kernel, cudaFuncAttributeMaxDynamicSharedMemorySize, QSMEM_BYTES);
        cudaFuncSetAttribute(attn_kernel, cudaFuncAttributeMaxDynamicSharedMemorySize, ATTN_SMEM_BYTES);
        attr_done = true;
    }

    pos_kernel<<<32, 1024>>>();
    pack_kernel<<<13312, 256>>>(x, k, v);
    wpack_kernel<<<144, 256>>>(Wq, Wfk, Wck, Wfv, Wcv);
    q_kernel<<<dim3(8, 2, 32), 256, QSMEM_BYTES>>>(bq);
    gated_kernel<<<dim3(8, 2, 64), 256, GSMEM_BYTES>>>(
        k, v, bfk, bck, bfv, bcv, kn, vn);
    attn_kernel<<<dim3(16, 32), 256, ATTN_SMEM_BYTES>>>(out2);
}

// round 5
// speedup vs baseline: 3.4366x; 1.0614x over previous
#include <cuda_runtime.h>
#include <math.h>
#include <stdint.h>

// ---------------------------------------------------------------------------
// Scratch (__device__ globals; no allocation allowed)
// ---------------------------------------------------------------------------
__device__ float g_pos[32 * 1024];              // [32 ch][1024], fp32
__device__ float g_x0[32 * 160 * 1024];         // tf32 [B][160][N]  (x|pos)
__device__ float g_kc[32 * 128 * 1024];         // tf32 k
__device__ float g_vc[32 * 128 * 1024];         // tf32 v
__device__ float g_q [32 * 128 * 1024];         // tf32 q
__device__ float g_Wq [128 * 160];              // tf32 weights
__device__ float g_Wfk[128 * 288];
__device__ float g_Wck[128 * 288];
__device__ float g_Wfv[128 * 288];
__device__ float g_Wcv[128 * 288];

// ---------------------------------------------------------------------------
// Helpers
// ---------------------------------------------------------------------------
__device__ __forceinline__ uint32_t f2tf(float x) {
    uint32_t u;
    asm("cvt.rna.tf32.f32 %0, %1;" : "=r"(u) : "f"(x));
    return u;
}
__device__ __forceinline__ float f2tff(float x) { return __uint_as_float(f2tf(x)); }

__device__ __forceinline__ void mma_tf32(
    float& d0, float& d1, float& d2, float& d3,
    uint32_t a0, uint32_t a1, uint32_t a2, uint32_t a3,
    uint32_t b0, uint32_t b1)
{
    asm volatile(
        "mma.sync.aligned.m16n8k8.row.col.f32.tf32.tf32.f32 "
        "{%0,%1,%2,%3}, {%4,%5,%6,%7}, {%8,%9}, {%0,%1,%2,%3};"
        : "+f"(d0), "+f"(d1), "+f"(d2), "+f"(d3)
        : "r"(a0), "r"(a1), "r"(a2), "r"(a3), "r"(b0), "r"(b1));
}

__device__ __forceinline__ void cpa16(uint32_t dst, const void* src) {
    asm volatile("cp.async.ca.shared.global [%0], [%1], 16;" :: "r"(dst), "l"(src));
}
#define CP_COMMIT() asm volatile("cp.async.commit_group;" ::: "memory")

// ---------------------------------------------------------------------------
// Positional embedding (faithful to numpy .view reinterpret)
// ---------------------------------------------------------------------------
__global__ void pos_kernel() {
    int idx = blockIdx.x * blockDim.x + threadIdx.x;
    if (idx >= 32 * 1024) return;
    int c = idx >> 10, n = idx & 1023;
    int y = n >> 5, x = n & 31;
    int i = (c < 16) ? (c * 32 + y) : ((c - 16) * 32 + x);
    int p = i >> 4, j = i & 15;
    float r = 0.0f;
    if (p != 0) {
        double denom = pow(10000.0, (double)(2 * (j >> 1)) / 16.0);
        double val = (double)p / denom;
        r = (j & 1) ? (float)cos(val) : (float)sin(val);
    }
    g_pos[idx] = r;
}

// ---------------------------------------------------------------------------
// Pack: tf32-round inputs AND weights into scratch (one launch)
// ---------------------------------------------------------------------------
__device__ __forceinline__ float4 tf4(float4 s) {
    s.x = f2tff(s.x); s.y = f2tff(s.y); s.z = f2tff(s.z); s.w = f2tff(s.w);
    return s;
}

#define PACK_NX0 (32 * 160 * 256)
#define PACK_NKV (32 * 128 * 256)
#define PACK_DATA (PACK_NX0 + 2 * PACK_NKV)
#define PACK_TOTAL (PACK_DATA + 128 * 288)

__global__ void pack_kernel(const float* __restrict__ x,
                            const float* __restrict__ k,
                            const float* __restrict__ v,
                            const float* __restrict__ Wq,
                            const float* __restrict__ Wfk, const float* __restrict__ Wck,
                            const float* __restrict__ Wfv, const float* __restrict__ Wcv)
{
    int i = blockIdx.x * blockDim.x + threadIdx.x;
    if (i < PACK_NX0) {
        int n4 = i & 255;
        int cb = i >> 8;
        int c = cb % 160, b = cb / 160;
        float4 s;
        if (c < 128)
            s = ((const float4*)x)[(size_t)(b * 128 + c) * 256 + n4];
        else
            s = ((const float4*)g_pos)[(c - 128) * 256 + n4];
        ((float4*)g_x0)[i] = tf4(s);
    } else if (i < PACK_NX0 + PACK_NKV) {
        int j = i - PACK_NX0;
        ((float4*)g_kc)[j] = tf4(((const float4*)k)[j]);
    } else if (i < PACK_DATA) {
        int j = i - PACK_NX0 - PACK_NKV;
        ((float4*)g_vc)[j] = tf4(((const float4*)v)[j]);
    } else {
        int j = i - PACK_DATA;                 // 0 .. 128*288-1
        if (j < 128 * 160) g_Wq[j] = f2tff(Wq[j]);
        g_Wfk[j] = f2tff(Wfk[j]);
        g_Wck[j] = f2tff(Wck[j]);
        g_Wfv[j] = f2tff(Wfv[j]);
        g_Wcv[j] = f2tff(Wcv[j]);
    }
}

// ---------------------------------------------------------------------------
// Fused GEMM kernel:
//   z in [0,64)  : gated highway update (z = b*2 + which), K=288, 9 steps
//   z in [64,96) : q = tf32(relu(Wq@x0+bq)) for b = z-64, K=160, 5 steps
// Both: CTA 64 out-rows x 128 cols, cp.async double-buffered, 8 warps.
// ---------------------------------------------------------------------------
#define GSA 36          // A smem row stride (words); 36 % 32 == 4
#define GSB 136         // B smem row stride; 136 % 32 == 8
#define GBUF 8960       // floats per gated pipeline buffer (2*64*GSA + 32*GSB)
#define GSMEM_BYTES (2 * GBUF * 4)
#define QBUF 6656       // floats per q pipeline buffer (64*GSA + 32*GSB)

__global__ __launch_bounds__(256, 2) void fused_gemm_kernel(
    const float* __restrict__ kOrig, const float* __restrict__ vOrig,
    const float* __restrict__ bfk, const float* __restrict__ bck,
    const float* __restrict__ bfv, const float* __restrict__ bcv,
    const float* __restrict__ bq,
    float* __restrict__ outk, float* __restrict__ outv)
{
    extern __shared__ float sm[];
    const int r0 = blockIdx.y * 64, n0 = blockIdx.x * 128;
    const int t = threadIdx.x, w = t >> 5, lane = t & 31;
    const int lr = lane >> 2, lc = lane & 3;
    const int wm = (w >> 2) * 32;   // 0 / 32
    const int wn = (w & 3) * 32;    // 0,32,64,96
    const uint32_t sbase = (uint32_t)__cvta_generic_to_shared(sm);

    if (blockIdx.z < 64) {
        // ================= gated body =================
        const int z = blockIdx.z, b = z >> 1, which = z & 1;
        const float* Wf   = which ? g_Wfv : g_Wfk;
        const float* Wc   = which ? g_Wcv : g_Wck;
        const float* bfp  = which ? bfv : bfk;
        const float* bcp  = which ? bcv : bck;
        const float* extc = which ? g_vc : g_kc;
        const float* extra = which ? vOrig : kOrig;
        float* out = which ? outv : outk;

        float accF[2][4][4], accC[2][4][4];
        #pragma unroll
        for (int mf = 0; mf < 2; mf++) {
            int rA = r0 + wm + mf * 16 + lr;
            float bf0 = bfp[rA], bf1 = bfp[rA + 8];
            float bc0 = bcp[rA], bc1 = bcp[rA + 8];
            #pragma unroll
            for (int nf = 0; nf < 4; nf++) {
                accF[mf][nf][0] = bf0; accF[mf][nf][1] = bf0;
                accF[mf][nf][2] = bf1; accF[mf][nf][3] = bf1;
                accC[mf][nf][0] = bc0; accC[mf][nf][1] = bc0;
                accC[mf][nf][2] = bc1; accC[mf][nf][3] = bc1;
            }
        }

        auto issue = [&](int it, int buf) {
            const int k0 = it * 32;
            const uint32_t base = sbase + buf * (GBUF * 4);
            #pragma unroll
            for (int h = 0; h < 2; h++) {
                int a = t + 256 * h;                // 0..511
                int r = a >> 3, c4 = a & 7;
                cpa16(base + (r * GSA + c4 * 4) * 4,
                      Wf + (size_t)(r0 + r) * 288 + k0 + c4 * 4);
                cpa16(base + (2304 + r * GSA + c4 * 4) * 4,
                      Wc + (size_t)(r0 + r) * 288 + k0 + c4 * 4);
            }
            #pragma unroll
            for (int h = 0; h < 4; h++) {
                int bi = t + 256 * h;               // 0..1023
                int r = bi >> 5, c4 = bi & 31;
                int row = k0 + r;
                const float* src = (row < 160)
                    ? (g_x0 + ((size_t)b * 160 + row) * 1024 + n0 + c4 * 4)
                    : (extc + ((size_t)b * 128 + (row - 160)) * 1024 + n0 + c4 * 4);
                cpa16(base + (4608 + r * GSB + c4 * 4) * 4, src);
            }
            CP_COMMIT();
        };

        issue(0, 0);
        #pragma unroll 1
        for (int it = 0; it < 9; it++) {
            if (it < 8) {
                issue(it + 1, (it + 1) & 1);
                asm volatile("cp.async.wait_group 1;" ::: "memory");
            } else {
                asm volatile("cp.async.wait_group 0;" ::: "memory");
            }
            __syncthreads();

            const float* AsF = sm + (it & 1) * GBUF;
            const float* AsC = AsF + 2304;
            const float* Bs  = AsF + 4608;

            #pragma unroll
            for (int kf = 0; kf < 4; kf++) {
                int kk = kf * 8;
                uint32_t aF[2][4], aC[2][4], bb[4][2];
                #pragma unroll
                for (int mf = 0; mf < 2; mf++) {
                    int base = (wm + mf * 16 + lr) * GSA + kk + lc;
                    aF[mf][0] = __float_as_uint(AsF[base]);
                    aF[mf][1] = __float_as_uint(AsF[base + 8 * GSA]);
                    aF[mf][2] = __float_as_uint(AsF[base + 4]);
                    aF[mf][3] = __float_as_uint(AsF[base + 8 * GSA + 4]);
                    aC[mf][0] = __float_as_uint(AsC[base]);
                    aC[mf][1] = __float_as_uint(AsC[base + 8 * GSA]);
                    aC[mf][2] = __float_as_uint(AsC[base + 4]);
                    aC[mf][3] = __float_as_uint(AsC[base + 8 * GSA + 4]);
                }
                #pragma unroll
                for (int nf = 0; nf < 4; nf++) {
                    int base = (kk + lc) * GSB + wn + nf * 8 + lr;
                    bb[nf][0] = __float_as_uint(Bs[base]);
                    bb[nf][1] = __float_as_uint(Bs[base + 4 * GSB]);
                }
                #pragma unroll
                for (int mf = 0; mf < 2; mf++)
                    #pragma unroll
                    for (int nf = 0; nf < 4; nf++) {
                        mma_tf32(accF[mf][nf][0], accF[mf][nf][1], accF[mf][nf][2], accF[mf][nf][3],
                                 aF[mf][0], aF[mf][1], aF[mf][2], aF[mf][3], bb[nf][0], bb[nf][1]);
                        mma_tf32(accC[mf][nf][0], accC[mf][nf][1], accC[mf][nf][2], accC[mf][nf][3],
                                 aC[mf][0], aC[mf][1], aC[mf][2], aC[mf][3], bb[nf][0], bb[nf][1]);
                    }
            }
            __syncthreads();
        }

        #pragma unroll
        for (int mf = 0; mf < 2; mf++) {
            int rA = r0 + wm + mf * 16 + lr;
            #pragma unroll
            for (int nf = 0; nf < 4; nf++) {
                int n = n0 + wn + nf * 8 + 2 * lc;
                #pragma unroll
                for (int h = 0; h < 2; h++) {
                    int row = rA + h * 8;
                    #pragma unroll
                    for (int j = 0; j < 2; j++) {
                        float F  = accF[mf][nf][2 * h + j];
                        float Cc = accC[mf][nf][2 * h + j];
                        float f  = 1.0f / (1.0f + __expf(-F));
                        float cc = fmaxf(Cc, 0.0f);
                        size_t off = ((size_t)(b * 128 + row)) * 1024 + n + j;
                        out[off] = f * extra[off] + cc;
                    }
                }
            }
        }
    } else {
        // ================= q body =================
        const int b = blockIdx.z - 64;

        float acc[2][4][4];
        #pragma unroll
        for (int mf = 0; mf < 2; mf++) {
            int rA = r0 + wm + mf * 16 + lr;
            float b0 = bq[rA], b1 = bq[rA + 8];
            #pragma unroll
            for (int nf = 0; nf < 4; nf++) {
                acc[mf][nf][0] = b0; acc[mf][nf][1] = b0;
                acc[mf][nf][2] = b1; acc[mf][nf][3] = b1;
            }
        }

        auto issue = [&](int it, int buf) {
            const int k0 = it * 32;
            const uint32_t base = sbase + buf * (QBUF * 4);
            #pragma unroll
            for (int h = 0; h < 2; h++) {
                int a = t + 256 * h;
                int r = a >> 3, c4 = a & 7;
                cpa16(base + (r * GSA + c4 * 4) * 4,
                      g_Wq + (size_t)(r0 + r) * 160 + k0 + c4 * 4);
            }
            #pragma unroll
            for (int h = 0; h < 4; h++) {
                int bi = t + 256 * h;
                int r = bi >> 5, c4 = bi & 31;
                cpa16(base + (2304 + r * GSB + c4 * 4) * 4,
                      g_x0 + ((size_t)b * 160 + k0 + r) * 1024 + n0 + c4 * 4);
            }
            CP_COMMIT();
        };

        issue(0, 0);
        #pragma unroll 1
        for (int it = 0; it < 5; it++) {
            if (it < 4) {
                issue(it + 1, (it + 1) & 1);
                asm volatile("cp.async.wait_group 1;" ::: "memory");
            } else {
                asm volatile("cp.async.wait_group 0;" ::: "memory");
            }
            __syncthreads();

            const float* As = sm + (it & 1) * QBUF;
            const float* Bs = As + 2304;

            #pragma unroll
            for (int kf = 0; kf < 4; kf++) {
                int kk = kf * 8;
                uint32_t aa[2][4], bb[4][2];
                #pragma unroll
                for (int mf = 0; mf < 2; mf++) {
                    int base = (wm + mf * 16 + lr) * GSA + kk + lc;
                    aa[mf][0] = __float_as_uint(As[base]);
                    aa[mf][1] = __float_as_uint(As[base + 8 * GSA]);
                    aa[mf][2] = __float_as_uint(As[base + 4]);
                    aa[mf][3] = __float_as_uint(As[base + 8 * GSA + 4]);
                }
                #pragma unroll
                for (int nf = 0; nf < 4; nf++) {
                    int base = (kk + lc) * GSB + wn + nf * 8 + lr;
                    bb[nf][0] = __float_as_uint(Bs[base]);
                    bb[nf][1] = __float_as_uint(Bs[base + 4 * GSB]);
                }
                #pragma unroll
                for (int mf = 0; mf < 2; mf++)
                    #pragma unroll
                    for (int nf = 0; nf < 4; nf++)
                        mma_tf32(acc[mf][nf][0], acc[mf][nf][1], acc[mf][nf][2], acc[mf][nf][3],
                                 aa[mf][0], aa[mf][1], aa[mf][2], aa[mf][3], bb[nf][0], bb[nf][1]);
            }
            __syncthreads();
        }

        #pragma unroll
        for (int mf = 0; mf < 2; mf++) {
            int rA = r0 + wm + mf * 16 + lr;
            #pragma unroll
            for (int nf = 0; nf < 4; nf++) {
                int n = n0 + wn + nf * 8 + 2 * lc;
                #pragma unroll
                for (int h = 0; h < 2; h++) {
                    int row = rA + h * 8;
                    #pragma unroll
                    for (int j = 0; j < 2; j++) {
                        float val = fmaxf(acc[mf][nf][2 * h + j], 0.0f);
                        g_q[((size_t)(b * 128 + row)) * 1024 + n + j] = f2tff(val);
                    }
                }
            }
        }
    }
}

// ---------------------------------------------------------------------------
// Causal attention, flash style, 512 threads (16 warps / 4 per SMSP).
// S phase : 4x4 warp grid, warp tile 16 q-rows x 16 keys.
// PV phase: warp tile 16 q-rows x 32 v-channels.
// Single-buffered K/V with hidden cp.async (K_{i+1} after S_i, V_{i+1}
// after PV_i). Softmax: 8 threads per row.
// ---------------------------------------------------------------------------
#define SQ 132
#define SK 72
#define SV 68
#define SP 68

#define OFF_QT 0
#define OFF_KS 8448                       // 128*SK = 9216
#define OFF_VS (OFF_KS + 128 * SK)        // 17664; 128*SV = 8704
#define OFF_PS (OFF_VS + 128 * SV)        // 26368; 64*SP = 4352
#define OFF_MAX (OFF_PS + 64 * SP)        // 30720
#define OFF_SUM (OFF_MAX + 64)
#define OFF_ALP (OFF_SUM + 64)
#define ATTN_SMEM_FLOATS (OFF_ALP + 64)   // 30912
#define ATTN_SMEM_BYTES (ATTN_SMEM_FLOATS * 4)

__global__ __launch_bounds__(512) void attn_kernel(float* __restrict__ out)
{
    extern __shared__ float sm[];
    float* Qt = sm + OFF_QT;
    float* Ks = sm + OFF_KS;
    float* Vs = sm + OFF_VS;
    float* Ps = sm + OFF_PS;
    float* sMax = sm + OFF_MAX;
    float* sSum = sm + OFF_SUM;
    float* sAlpha = sm + OFF_ALP;

    const int b = blockIdx.y;
    const int bx = 15 - blockIdx.x;       // heavy blocks first
    const int n0 = bx * 64;
    const int t = threadIdx.x, w = t >> 5, lane = t & 31;
    const int lr = lane >> 2, lc = lane & 3;
    const int wm  = (w >> 2) * 16;        // 16 q-rows per warp
    const int wnS = (w & 3) * 16;         // S-phase key cols
    const int wnV = (w & 3) * 32;         // PV-phase v-channels
    const float scale = 0.08838834764831845f;
    const uint32_t sbase = (uint32_t)__cvta_generic_to_shared(sm);

    auto issue_k = [&](int mt) {
        const int m0 = mt * 64;
        const uint32_t kb = sbase + OFF_KS * 4;
        #pragma unroll
        for (int h = 0; h < 4; h++) {
            int idx = t + 512 * h;            // 0..2047
            int c = idx >> 4, m4 = idx & 15;
            cpa16(kb + (c * SK + m4 * 4) * 4,
                  g_kc + ((size_t)(b * 128 + c)) * 1024 + m0 + m4 * 4);
        }
        CP_COMMIT();
    };
    auto issue_v = [&](int mt) {
        const int m0 = mt * 64;
        const uint32_t vb = sbase + OFF_VS * 4;
        #pragma unroll
        for (int h = 0; h < 4; h++) {
            int idx = t + 512 * h;
            int c = idx >> 4, m4 = idx & 15;
            cpa16(vb + (c * SV + m4 * 4) * 4,
                  g_vc + ((size_t)(b * 128 + c)) * 1024 + m0 + m4 * 4);
        }
        CP_COMMIT();
    };

    issue_k(0);
    issue_v(0);

    // Q tile transposed (g_q already tf32) — overlaps with K0/V0 loads
    #pragma unroll
    for (int e = 0; e < 16; e++) {
        int idx = t + 512 * e;
        int c = idx >> 6, i = idx & 63;
        Qt[i * SQ + c] = g_q[((size_t)(b * 128 + c)) * 1024 + n0 + i];
    }
    if (t < 64) { sMax[t] = -1e30f; sSum[t] = 0.0f; }

    float O[4][4];
    #pragma unroll
    for (int nf = 0; nf < 4; nf++)
        #pragma unroll
        for (int j = 0; j < 4; j++) O[nf][j] = 0.0f;

    #pragma unroll 1
    for (int mt = 0; mt <= bx; mt++) {
        // K_mt ready (pending {K_mt, V_mt} -> wait<=1 drains K_mt)
        asm volatile("cp.async.wait_group 1;" ::: "memory");
        __syncthreads();

        // ---- S = Q^T K (warp tile 16x16) ----
        float S[2][4];
        #pragma unroll
        for (int nf = 0; nf < 2; nf++)
            #pragma unroll
            for (int j = 0; j < 4; j++) S[nf][j] = 0.0f;

        #pragma unroll
        for (int kf = 0; kf < 16; kf++) {
            int kc = kf * 8;
            int abase = (wm + lr) * SQ + kc + lc;
            uint32_t a0 = __float_as_uint(Qt[abase]);
            uint32_t a1 = __float_as_uint(Qt[abase + 8 * SQ]);
            uint32_t a2 = __float_as_uint(Qt[abase + 4]);
            uint32_t a3 = __float_as_uint(Qt[abase + 8 * SQ + 4]);
            #pragma unroll
            for (int nf = 0; nf < 2; nf++) {
                int bbase = (kc + lc) * SK + wnS + nf * 8 + lr;
                uint32_t b0 = __float_as_uint(Ks[bbase]);
                uint32_t b1 = __float_as_uint(Ks[bbase + 4 * SK]);
                mma_tf32(S[nf][0], S[nf][1], S[nf][2], S[nf][3], a0, a1, a2, a3, b0, b1);
            }
        }
        #pragma unroll
        for (int nf = 0; nf < 2; nf++) {
            int col = wnS + nf * 8 + 2 * lc;
            int row = wm + lr;
            Ps[row * SP + col]           = S[nf][0] * scale;
            Ps[row * SP + col + 1]       = S[nf][1] * scale;
            Ps[(row + 8) * SP + col]     = S[nf][2] * scale;
            Ps[(row + 8) * SP + col + 1] = S[nf][3] * scale;
        }
        __syncthreads();            // S reads of Ks done, Ps visible

        // Prefetch next K (hidden behind softmax + PV)
        if (mt < bx) issue_k(mt + 1);

        // ---- Online softmax: 8 threads per row ----
        {
            int r = t >> 3, qd = t & 7;
            bool diag = (mt == bx);
            float vals[8];
            float tm = -1e30f;
            #pragma unroll
            for (int j = 0; j < 8; j++) {
                int m = qd * 8 + j;
                float s = Ps[r * SP + m];
                if (diag && m > r) s = -1e30f;
                vals[j] = s;
                tm = fmaxf(tm, s);
            }
            tm = fmaxf(tm, __shfl_xor_sync(0xffffffffu, tm, 1));
            tm = fmaxf(tm, __shfl_xor_sync(0xffffffffu, tm, 2));
            tm = fmaxf(tm, __shfl_xor_sync(0xffffffffu, tm, 4));
            float rm = sMax[r];
            float nm = fmaxf(rm, tm);
            float ps = 0.0f;
            #pragma unroll
            for (int j = 0; j < 8; j++) {
                float p = f2tff(__expf(vals[j] - nm));
                Ps[r * SP + qd * 8 + j] = p;
                ps += p;
            }
            ps += __shfl_xor_sync(0xffffffffu, ps, 1);
            ps += __shfl_xor_sync(0xffffffffu, ps, 2);
            ps += __shfl_xor_sync(0xffffffffu, ps, 4);
            float alpha = __expf(rm - nm);
            if (qd == 0) {
                sSum[r] = sSum[r] * alpha + ps;
                sMax[r] = nm;
                sAlpha[r] = alpha;
            }
        }

        // V_mt ready (pending {V_mt, K_{mt+1}} -> wait<=1; last iter wait 0)
        if (mt < bx) {
            asm volatile("cp.async.wait_group 1;" ::: "memory");
        } else {
            asm volatile("cp.async.wait_group 0;" ::: "memory");
        }
        __syncthreads();            // P + stats visible, V ready

        // ---- O = O*alpha + P @ V^T (warp tile 16 rows x 32 channels) ----
        float aLo = sAlpha[wm + lr], aHi = sAlpha[wm + lr + 8];
        #pragma unroll
        for (int nf = 0; nf < 4; nf++) {
            O[nf][0] *= aLo; O[nf][1] *= aLo;
            O[nf][2] *= aHi; O[nf][3] *= aHi;
        }
        #pragma unroll
        for (int kf = 0; kf < 8; kf++) {
            int kc = kf * 8;
            int abase = (wm + lr) * SP + kc + lc;
            uint32_t a0 = __float_as_uint(Ps[abase]);
            uint32_t a1 = __float_as_uint(Ps[abase + 8 * SP]);
            uint32_t a2 = __float_as_uint(Ps[abase + 4]);
            uint32_t a3 = __float_as_uint(Ps[abase + 8 * SP + 4]);
            #pragma unroll
            for (int nf = 0; nf < 4; nf++) {
                int vb = wnV + nf * 8 + lr;
                int bbase = vb * SV + kc + lc;
                uint32_t b0 = __float_as_uint(Vs[bbase]);
                uint32_t b1 = __float_as_uint(Vs[bbase + 4]);
                mma_tf32(O[nf][0], O[nf][1], O[nf][2], O[nf][3], a0, a1, a2, a3, b0, b1);
            }
        }
        __syncthreads();            // PV reads of Vs done

        // Prefetch next V (hidden behind next S phase)
        if (mt < bx) issue_v(mt + 1);
    }

    float invLo = 1.0f / sSum[wm + lr];
    float invHi = 1.0f / sSum[wm + lr + 8];
    int nLo = n0 + wm + lr, nHi = nLo + 8;
    #pragma unroll
    for (int nf = 0; nf < 4; nf++) {
        int vc = wnV + nf * 8 + 2 * lc;
        out[((size_t)(b * 128 + vc))     * 1024 + nLo] = O[nf][0] * invLo;
        out[((size_t)(b * 128 + vc + 1)) * 1024 + nLo] = O[nf][1] * invLo;
        out[((size_t)(b * 128 + vc))     * 1024 + nHi] = O[nf][2] * invHi;
        out[((size_t)(b * 128 + vc + 1)) * 1024 + nHi] = O[nf][3] * invHi;
    }
}

// ---------------------------------------------------------------------------
// Launch (single stream, graph-capturable)
// ---------------------------------------------------------------------------
extern "C" void kernel_launch(void* const* d_in, const int* in_sizes, int n_in,
                              void* d_out, int out_size)
{
    const float* x   = (const float*)d_in[0];
    const float* k   = (const float*)d_in[1];
    const float* v   = (const float*)d_in[2];
    const float* Wq  = (const float*)d_in[3];
    const float* bq  = (const float*)d_in[4];
    const float* Wfk = (const float*)d_in[5];
    const float* bfk = (const float*)d_in[6];
    const float* Wck = (const float*)d_in[7];
    const float* bck = (const float*)d_in[8];
    const float* Wfv = (const float*)d_in[9];
    const float* bfv = (const float*)d_in[10];
    const float* Wcv = (const float*)d_in[11];
    const float* bcv = (const float*)d_in[12];

    float* out2 = (float*)d_out;
    float* kn   = out2 + (size_t)32 * 128 * 1024;
    float* vn   = kn   + (size_t)32 * 128 * 1024;

    cudaFuncSetAttribute(fused_gemm_kernel, cudaFuncAttributeMaxDynamicSharedMemorySize, GSMEM_BYTES);
    cudaFuncSetAttribute(attn_kernel, cudaFuncAttributeMaxDynamicSharedMemorySize, ATTN_SMEM_BYTES);

    pos_kernel<<<32, 1024>>>();
    pack_kernel<<<(PACK_TOTAL + 255) / 256, 256>>>(x, k, v, Wq, Wfk, Wck, Wfv, Wcv);
    fused_gemm_kernel<<<dim3(8, 2, 96), 256, GSMEM_BYTES>>>(
        k, v, bfk, bck, bfv, bcv, bq, kn, vn);
    attn_kernel<<<dim3(16, 32), 512, ATTN_SMEM_BYTES>>>(out2);
}